// round 14
// baseline (speedup 1.0000x reference)
#include <cuda_runtime.h>
#include <cuda_fp16.h>
#include <cstdint>

#define VOCAB 50257
#define FEAT  512
#define EPS   1e-12f

// Precomputed normalized table in fp16: 50257*512*2 B = 51.5 MB (L2-resident
// between build and gather; writes never drain to DRAM).
__device__ __half g_nt[(size_t)VOCAB * FEAT];

// ---------------------------------------------------------------------------
// Kernel 1: build normalized table, cp.async edition.
//  - VT=32 vocab rows/block; fp32 tile in DYNAMIC shared (32 x 514 floats,
//    65792 B; even stride -> 8B-aligned float2 rows, 2-way bank conflicts
//    on both phases — acceptable).
//  - Each thread issues 32 independent 4B cp.async copies (transposed
//    scatter into smem), zero register staging, MLP=32/thread; one
//    wait_group + barrier. Global side stays 128B/warp coalesced.
//  - Norm phase: warp w owns rows 2w/2w+1; float2 reads + bias, fp32
//    sumsq reduce, fp16 table write coalesced.
// ---------------------------------------------------------------------------
#define VT 32
#define SF 514   // floats per shared row (stride)

__device__ __forceinline__ uint32_t smem_u32(const void* p) {
    uint32_t a;
    asm("{ .reg .u64 t; cvta.to.shared.u64 t, %1; cvt.u32.u64 %0, t; }"
        : "=r"(a) : "l"(p));
    return a;
}

__global__ __launch_bounds__(512) void build_nt_kernel(
    const float* __restrict__ W, const float* __restrict__ b)
{
    extern __shared__ float sh[];        // VT*SF floats = 65792 B (dynamic)
    __shared__ float shb[FEAT];          // 2048 B static

    const int tid  = threadIdx.x;
    const int w    = tid >> 5;           // 0..15
    const int lane = tid & 31;
    const int v0   = blockIdx.x * VT;

    shb[tid] = __ldg(&b[tid]);

    const int v = v0 + lane;
    const int srcbytes = (v < VOCAB) ? 4 : 0;   // 0 -> zero-fill dst
    const float* __restrict__ Wp = W + v;
    const uint32_t sbase = smem_u32(sh) + (uint32_t)(lane * SF) * 4u;

    // 32 independent 4B async copies per thread: f = w + 16*it.
    #pragma unroll
    for (int it = 0; it < 32; it++) {
        const int f = w + 16 * it;
        asm volatile("cp.async.ca.shared.global [%0], [%1], 4, %2;"
                     :: "r"(sbase + (uint32_t)f * 4u),
                        "l"(Wp + (size_t)f * VOCAB),
                        "r"(srcbytes));
    }
    asm volatile("cp.async.commit_group;");
    asm volatile("cp.async.wait_group 0;" ::: "memory");
    __syncthreads();

    // Norm + write: warp w owns vocab rows 2w, 2w+1.
    #pragma unroll
    for (int rr = 0; rr < 2; rr++) {
        const int r  = 2 * w + rr;
        const int vr = v0 + r;
        if (vr >= VOCAB) continue;

        const float2* row2  = (const float2*)(sh + (size_t)r * SF);
        const float2* bias2 = (const float2*)shb;

        float s = 0.0f;
        float2 xv[8];
        #pragma unroll
        for (int k = 0; k < 8; k++) {
            const int p = lane + 32 * k;       // feature pair index 0..255
            float2 t  = row2[p];
            float2 bb = bias2[p];
            t.x += bb.x; t.y += bb.y;
            xv[k] = t;
            s = fmaf(t.x, t.x, s);
            s = fmaf(t.y, t.y, s);
        }
        #pragma unroll
        for (int off = 16; off > 0; off >>= 1)
            s += __shfl_xor_sync(0xFFFFFFFFu, s, off);

        const float rinv = 1.0f / fmaxf(sqrtf(s), EPS);

        __half2* dst = (__half2*)(g_nt + (size_t)vr * FEAT);
        #pragma unroll
        for (int k = 0; k < 8; k++) {
            const int p = lane + 32 * k;
            float2 t = make_float2(xv[k].x * rinv, xv[k].y * rinv);
            dst[p] = __float22half2_rn(t);
        }
    }
}

// ---------------------------------------------------------------------------
// Kernel 2: gather — EXACT R8/R10 version (51.6-52.4us, pinned at the
// write-mix bandwidth ceiling across 4 variants). LDG.64 table loads are
// width-matched to the fp16->fp32 expansion so STG.128 stays contiguous.
// FROZEN — do not touch (R9 lesson).
// ---------------------------------------------------------------------------
__global__ __launch_bounds__(512) void gather_kernel(
    const int* __restrict__ ids, float* __restrict__ out, int ntok)
{
    __shared__ int sh_ids[32];

    const int tid  = threadIdx.x;
    const int w    = tid >> 5;
    const int lane = tid & 31;
    const int base = blockIdx.x * 32;

    if (tid < 32) {
        const int t = base + tid;
        sh_ids[tid] = (t < ntok) ? __ldg(&ids[t]) : 0;
    }
    __syncthreads();

    const int id0 = sh_ids[2 * w];
    const int id1 = sh_ids[2 * w + 1];
    const uint2* __restrict__ s0 = (const uint2*)(g_nt + (size_t)id0 * FEAT);
    const uint2* __restrict__ s1 = (const uint2*)(g_nt + (size_t)id1 * FEAT);

    uint2 u[2][4];
    #pragma unroll
    for (int k = 0; k < 4; k++) u[0][k] = __ldg(&s0[lane + 32 * k]);
    #pragma unroll
    for (int k = 0; k < 4; k++) u[1][k] = __ldg(&s1[lane + 32 * k]);

    const int t0 = base + 2 * w;
    #pragma unroll
    for (int tk = 0; tk < 2; tk++) {
        const int t = t0 + tk;
        if (t >= ntok) break;
        float4* __restrict__ dst = (float4*)(out + (size_t)t * FEAT);
        #pragma unroll
        for (int k = 0; k < 4; k++) {
            __half2 h0 = *reinterpret_cast<__half2*>(&u[tk][k].x);
            __half2 h1 = *reinterpret_cast<__half2*>(&u[tk][k].y);
            float2 f0 = __half22float2(h0);
            float2 f1 = __half22float2(h1);
            __stcs(&dst[lane + 32 * k], make_float4(f0.x, f0.y, f1.x, f1.y));
        }
    }
}

// ---------------------------------------------------------------------------
// Launch
//   d_in[0] = token_ids int32 [32*4096]
//   d_in[1] = W float32 [512*50257]
//   d_in[2] = b float32 [512]
//   d_out   = float32 [32*4096*512]
// ---------------------------------------------------------------------------
extern "C" void kernel_launch(void* const* d_in, const int* in_sizes, int n_in,
                              void* d_out, int out_size)
{
    const int*   ids = (const int*)d_in[0];
    const float* W   = (const float*)d_in[1];
    const float* b   = (const float*)d_in[2];
    float*       out = (float*)d_out;

    const int ntok = in_sizes[0];   // 131072

    const int dyn_smem = VT * SF * (int)sizeof(float);   // 65792 B
    // Attribute set (idempotent host call, no allocation; executed at call /
    // capture time, persists for replays).
    cudaFuncSetAttribute(build_nt_kernel,
                         cudaFuncAttributeMaxDynamicSharedMemorySize, dyn_smem);

    const int nt_blocks = (VOCAB + VT - 1) / VT;   // 1571
    build_nt_kernel<<<nt_blocks, 512, dyn_smem>>>(W, b);

    const int g_blocks = (ntok + 31) / 32;         // 4096
    gather_kernel<<<g_blocks, 512>>>(ids, out, ntok);
}

// round 17
// speedup vs baseline: 1.2895x; 1.2895x over previous
#include <cuda_runtime.h>
#include <cuda_fp16.h>
#include <cstdint>

#define VOCAB 50257
#define FEAT  512
#define EPS   1e-12f

// Precomputed normalized table in fp16: 50257*512*2 B = 51.5 MB.
// Written and read at L2::evict_last priority (via createpolicy + cache_hint,
// the width-agnostic form) so it stays L2-resident across build -> gather;
// the 256 MB output stream is evict-first via __stcs.
__device__ __half g_nt[(size_t)VOCAB * FEAT];

// ---------------------------------------------------------------------------
// L2 eviction-priority helpers (policy form: legal at any access width).
// ---------------------------------------------------------------------------
__device__ __forceinline__ uint64_t evict_last_policy() {
    uint64_t pol;
    asm("createpolicy.fractional.L2::evict_last.b64 %0, 1.0;" : "=l"(pol));
    return pol;
}
__device__ __forceinline__ void st_hint_u32(void* p, uint32_t v, uint64_t pol) {
    asm volatile("st.global.L2::cache_hint.u32 [%0], %1, %2;"
                 :: "l"(p), "r"(v), "l"(pol) : "memory");
}
__device__ __forceinline__ uint2 ld_hint_u64(const void* p, uint64_t pol) {
    uint2 r;
    asm volatile("ld.global.nc.L2::cache_hint.v2.u32 {%0, %1}, [%2], %3;"
                 : "=r"(r.x), "=r"(r.y) : "l"(p), "l"(pol));
    return r;
}

// ---------------------------------------------------------------------------
// Kernel 1: build normalized table (R10 proven structure + evict_last stores).
//   Load : warp w owns feature PAIRS p = w + 16*jj; two 128B coalesced loads
//          per pair, 16 LDGs in flight per batch; pack half2; one full-width
//          STS per pair.
//   Norm : warp w reduces vocab rows 2w / 2w+1, writes fp16 rows coalesced
//          at evict_last priority (table pinned for the gather).
// ---------------------------------------------------------------------------
#define VT 32
#define S2 257   // half2 per shared row (stride); odd -> bank-conflict-free

__global__ __launch_bounds__(512) void build_nt_kernel(
    const float* __restrict__ W, const float* __restrict__ b)
{
    __shared__ __half2 sh2[VT * S2];   // 32896 B
    __shared__ float   shb[FEAT];      // 2048 B

    const int tid  = threadIdx.x;
    const int w    = tid >> 5;         // 0..15
    const int lane = tid & 31;
    const int v0   = blockIdx.x * VT;

    shb[tid] = __ldg(&b[tid]);
    __syncthreads();

    const int v = v0 + lane;
    const bool vok = (v < VOCAB);
    const float* __restrict__ Wp = W + v;

    float a0[8], a1[8];
    #pragma unroll
    for (int half_ = 0; half_ < 2; half_++) {
        const int pb = half_ * 8;
        #pragma unroll
        for (int j = 0; j < 8; j++) {
            const int p = w + 16 * (pb + j);          // pair index 0..255
            a0[j] = vok ? __ldcs(&Wp[(size_t)(2 * p)     * VOCAB]) : 0.0f;
            a1[j] = vok ? __ldcs(&Wp[(size_t)(2 * p + 1) * VOCAB]) : 0.0f;
        }
        #pragma unroll
        for (int j = 0; j < 8; j++) {
            const int p = w + 16 * (pb + j);
            float2 pv = make_float2(a0[j] + shb[2 * p], a1[j] + shb[2 * p + 1]);
            sh2[(size_t)lane * S2 + p] = __float22half2_rn(pv);
        }
    }
    __syncthreads();

    const uint64_t pol = evict_last_policy();

    #pragma unroll
    for (int rr = 0; rr < 2; rr++) {
        const int r  = 2 * w + rr;
        const int vr = v0 + r;
        if (vr >= VOCAB) continue;

        const __half2* row = sh2 + (size_t)r * S2;

        float s = 0.0f;
        float2 fv[8];
        #pragma unroll
        for (int k = 0; k < 8; k++) {
            fv[k] = __half22float2(row[lane + 32 * k]);
            s = fmaf(fv[k].x, fv[k].x, s);
            s = fmaf(fv[k].y, fv[k].y, s);
        }
        #pragma unroll
        for (int off = 16; off > 0; off >>= 1)
            s += __shfl_xor_sync(0xFFFFFFFFu, s, off);

        const float rinv = 1.0f / fmaxf(sqrtf(s), EPS);

        __half2* dst = (__half2*)(g_nt + (size_t)vr * FEAT);
        #pragma unroll
        for (int k = 0; k < 8; k++) {
            float2 p = make_float2(fv[k].x * rinv, fv[k].y * rinv);
            __half2 h = __float22half2_rn(p);
            st_hint_u32(&dst[lane + 32 * k],
                        *reinterpret_cast<uint32_t*>(&h), pol);
        }
    }
}

// ---------------------------------------------------------------------------
// Kernel 2: gather — R8/R10 structure (pinned at the write-mix ceiling);
// table loads carry the evict_last policy (kills the ~18 MB DRAM re-reads).
// LDG.64 width stays load-matched to the fp16->fp32 expansion so STG.128
// stays perfectly contiguous (R9 lesson: do not widen).
// ---------------------------------------------------------------------------
__global__ __launch_bounds__(512) void gather_kernel(
    const int* __restrict__ ids, float* __restrict__ out, int ntok)
{
    __shared__ int sh_ids[32];

    const int tid  = threadIdx.x;
    const int w    = tid >> 5;
    const int lane = tid & 31;
    const int base = blockIdx.x * 32;

    if (tid < 32) {
        const int t = base + tid;
        sh_ids[tid] = (t < ntok) ? __ldg(&ids[t]) : 0;
    }
    __syncthreads();

    const uint64_t pol = evict_last_policy();

    const int id0 = sh_ids[2 * w];
    const int id1 = sh_ids[2 * w + 1];
    const uint2* __restrict__ s0 = (const uint2*)(g_nt + (size_t)id0 * FEAT);
    const uint2* __restrict__ s1 = (const uint2*)(g_nt + (size_t)id1 * FEAT);

    uint2 u[2][4];
    #pragma unroll
    for (int k = 0; k < 4; k++) u[0][k] = ld_hint_u64(&s0[lane + 32 * k], pol);
    #pragma unroll
    for (int k = 0; k < 4; k++) u[1][k] = ld_hint_u64(&s1[lane + 32 * k], pol);

    const int t0 = base + 2 * w;
    #pragma unroll
    for (int tk = 0; tk < 2; tk++) {
        const int t = t0 + tk;
        if (t >= ntok) break;
        float4* __restrict__ dst = (float4*)(out + (size_t)t * FEAT);
        #pragma unroll
        for (int k = 0; k < 4; k++) {
            __half2 h0 = *reinterpret_cast<__half2*>(&u[tk][k].x);
            __half2 h1 = *reinterpret_cast<__half2*>(&u[tk][k].y);
            float2 f0 = __half22float2(h0);
            float2 f1 = __half22float2(h1);
            __stcs(&dst[lane + 32 * k], make_float4(f0.x, f0.y, f1.x, f1.y));
        }
    }
}

// ---------------------------------------------------------------------------
// Launch
//   d_in[0] = token_ids int32 [32*4096]
//   d_in[1] = W float32 [512*50257]
//   d_in[2] = b float32 [512]
//   d_out   = float32 [32*4096*512]
// ---------------------------------------------------------------------------
extern "C" void kernel_launch(void* const* d_in, const int* in_sizes, int n_in,
                              void* d_out, int out_size)
{
    const int*   ids = (const int*)d_in[0];
    const float* W   = (const float*)d_in[1];
    const float* b   = (const float*)d_in[2];
    float*       out = (float*)d_out;

    const int ntok = in_sizes[0];   // 131072

    const int nt_blocks = (VOCAB + VT - 1) / VT;   // 1571
    build_nt_kernel<<<nt_blocks, 512>>>(W, b);

    const int g_blocks = (ntok + 31) / 32;         // 4096
    gather_kernel<<<g_blocks, 512>>>(ids, out, ntok);
}